// round 8
// baseline (speedup 1.0000x reference)
#include <cuda_runtime.h>

// Problem shapes (fixed by setup_inputs)
#define BB 64
#define TT 1024
#define JJ 32
#define TOTAL (BB * TT * JJ)

// Scratch: per-(b,t) root trajectory + per-batch ready flags.
__device__ float4 d_traj[BB * TT];
__device__ int    d_flag[BB];

// Rotate point p by unit quaternion q=(w,x,y,z): p' = p + w*t + u×t, t = 2*(u×p)
__device__ __forceinline__ void qrotate(float w, float x, float y, float z,
                                        float px, float py, float pz,
                                        float& ox, float& oy, float& oz) {
    float tx = 2.0f * (y * pz - z * py);
    float ty = 2.0f * (z * px - x * pz);
    float tz = 2.0f * (x * py - y * px);
    ox = px + w * tx + (y * tz - z * ty);
    oy = py + w * ty + (z * tx - x * tz);
    oz = pz + w * tz + (x * ty - y * tx);
}

__device__ __forceinline__ int ld_acquire_gpu(const int* p) {
    int v;
    asm volatile("ld.acquire.gpu.b32 %0, [%1];" : "=r"(v) : "l"(p) : "memory");
    return v;
}
__device__ __forceinline__ void st_release_gpu(int* p, int v) {
    asm volatile("st.release.gpu.b32 [%0], %1;" :: "l"(p), "r"(v) : "memory");
}

// One kernel. Blocks [0,64): per-batch trajectory scan (producers, dispatched
// first => wave-1 resident => no deadlock). Blocks [64, 64+8192): elementwise
// main work (R1 layout: 1 element/thread, scalar pos, float4 rot), waiting on
// the producer flag only right before the traj add.
__global__ void __launch_bounds__(256)
fused_kernel(const float* __restrict__ glb_pos,
             const float* __restrict__ glb_rot,
             const float* __restrict__ glb_vel,
             const float* __restrict__ root,
             float* __restrict__ out) {
    const int bid = blockIdx.x;
    const int tid = threadIdx.x;

    if (bid < BB) {
        // ---------- producer: scan for batch b ----------
        const int b = bid;
        __shared__ float wsx[8], wsy[8], wsz[8];
        const int lane = tid & 31, warp = tid >> 5;

        // e[t] = rot(inv[t-1], vel[t-1, joint0]), e[0] = 0; 4 t-steps per thread
        float ex[4], ey[4], ez[4];
        #pragma unroll
        for (int k = 0; k < 4; k++) {
            int t = tid * 4 + k;
            ex[k] = ey[k] = ez[k] = 0.0f;
            if (t >= 1) {
                int s = t - 1;
                float4 q = __ldg((const float4*)(root + (size_t)(b * TT + s) * 4));
                float4 v = __ldg((const float4*)(glb_vel +
                                 (size_t)(b * (TT - 1) + s) * JJ * 3));  // joint0 (+pad)
                qrotate(q.x, -q.y, -q.z, -q.w, v.x, v.y, v.z, ex[k], ey[k], ez[k]);
            }
        }
        // local inclusive
        #pragma unroll
        for (int k = 1; k < 4; k++) { ex[k] += ex[k-1]; ey[k] += ey[k-1]; ez[k] += ez[k-1]; }
        const float thx = ex[3], thy = ey[3], thz = ez[3];

        // warp-inclusive scan of thread sums
        float sx = thx, sy = thy, sz = thz;
        #pragma unroll
        for (int d = 1; d < 32; d <<= 1) {
            float nx = __shfl_up_sync(0xffffffffu, sx, d);
            float ny = __shfl_up_sync(0xffffffffu, sy, d);
            float nz = __shfl_up_sync(0xffffffffu, sz, d);
            if (lane >= d) { sx += nx; sy += ny; sz += nz; }
        }
        if (lane == 31) { wsx[warp] = sx; wsy[warp] = sy; wsz[warp] = sz; }
        __syncthreads();
        if (tid == 0) {
            float ax = 0, ay = 0, az = 0;
            #pragma unroll
            for (int w2 = 0; w2 < 8; w2++) {
                float tx = wsx[w2], ty = wsy[w2], tz = wsz[w2];
                wsx[w2] = ax; wsy[w2] = ay; wsz[w2] = az;
                ax += tx; ay += ty; az += tz;
            }
        }
        __syncthreads();

        // base = rot(inv[b,0], pos[b,0,joint0])  (redundant per thread; L2 broadcast)
        float4 q0 = __ldg((const float4*)(root + (size_t)b * TT * 4));
        float4 p0 = __ldg((const float4*)(glb_pos + (size_t)b * TT * JJ * 3));
        float bx, by, bz;
        qrotate(q0.x, -q0.y, -q0.z, -q0.w, p0.x, p0.y, p0.z, bx, by, bz);

        const float offx = bx + wsx[warp] + (sx - thx);
        const float offy = by + wsy[warp] + (sy - thy);
        const float offz = bz + wsz[warp] + (sz - thz);
        #pragma unroll
        for (int k = 0; k < 4; k++) {
            d_traj[b * TT + tid * 4 + k] =
                make_float4(offx + ex[k], offy + ey[k], offz + ez[k], 0.0f);
        }

        __threadfence();
        __syncthreads();
        if (tid == 0) st_release_gpu(&d_flag[b], 1);
        return;
    }

    // ---------- consumer: main elementwise work (R1 layout) ----------
    const int idx  = (bid - BB) * 256 + tid;   // 0 .. TOTAL-1
    const int pair = idx >> 5;                 // (b*T + t)
    const int b    = idx >> 15;                // batch (32768 elems per batch)

    // issue independent loads first
    const float4 q = __ldg((const float4*)(root + (size_t)pair * 4));
    const float4 g = __ldg((const float4*)(glb_rot + (size_t)idx * 4));
    const float* p = glb_pos + (size_t)idx * 3;
    const float px = __ldg(p), py = __ldg(p + 1), pz = __ldg(p + 2);

    const float w = q.x, x = -q.y, y = -q.z, z = -q.w;

    // rot path: standardize(inv ⊗ glb_rot)
    {
        float rw = w * g.x - x * g.y - y * g.z - z * g.w;
        float rx = w * g.y + x * g.x + y * g.w - z * g.z;
        float ry = w * g.z - x * g.w + y * g.x + z * g.y;
        float rz = w * g.w + x * g.z - y * g.y + z * g.x;
        float s = (rw < 0.0f) ? -1.0f : 1.0f;
        ((float4*)(out + (size_t)TOTAL * 3))[idx] =
            make_float4(s * rw, s * rx, s * ry, s * rz);
    }

    // pos rotate (independent of traj)
    float ox, oy, oz;
    qrotate(w, x, y, z, px, py, pz, ox, oy, oz);

    // wait for this batch's trajectory (almost always already set)
    while (ld_acquire_gpu(&d_flag[b]) == 0) { }

    const float4 tr = __ldg(&d_traj[pair]);
    float* op = out + (size_t)idx * 3;
    op[0] = ox + tr.x;
    op[1] = oy;
    op[2] = oz + tr.z;
}

extern "C" void kernel_launch(void* const* d_in, const int* in_sizes, int n_in,
                              void* d_out, int out_size) {
    const float* glb_pos = (const float*)d_in[0];
    const float* glb_rot = (const float*)d_in[1];
    const float* glb_vel = (const float*)d_in[2];
    const float* root    = (const float*)d_in[3];
    float* out = (float*)d_out;

    void* fp = nullptr;
    cudaGetSymbolAddress(&fp, d_flag);
    cudaMemsetAsync(fp, 0, sizeof(int) * BB, 0);   // graph-capturable memset node

    const int grid = BB + TOTAL / 256;   // 64 producer blocks + 8192 consumer blocks
    fused_kernel<<<grid, 256>>>(glb_pos, glb_rot, glb_vel, root, out);
}

// round 13
// speedup vs baseline: 1.6915x; 1.6915x over previous
#include <cuda_runtime.h>

// Problem shapes (fixed by setup_inputs)
#define BB 64
#define TT 1024
#define JJ 32
#define TOTAL (BB * TT * JJ)

// Scratch: per-(b,t) root trajectory, float4-padded. 4 MB.
__device__ float4 d_traj[BB * TT];

// Rotate point p by unit quaternion q=(w,x,y,z): p' = p + w*t + u×t, t = 2*(u×p)
__device__ __forceinline__ void qrotate(float w, float x, float y, float z,
                                        float px, float py, float pz,
                                        float& ox, float& oy, float& oz) {
    float tx = 2.0f * (y * pz - z * py);
    float ty = 2.0f * (z * px - x * pz);
    float tz = 2.0f * (x * py - y * px);
    ox = px + w * tx + (y * tz - z * ty);
    oy = py + w * ty + (z * tx - x * tz);
    oz = pz + w * tz + (x * ty - y * tx);
}

// Kernel 1: per-batch trajectory scan. 64 blocks x 256 threads, 4 t-steps per
// thread: serial local prefix + shfl warp scan + 8-entry smem combine.
// traj[b,t] = rot(inv[b,0], pos[b,0,j0]) + sum_{s<t} rot(inv[b,s], vel[b,s,j0])
__global__ void __launch_bounds__(256)
traj_scan_kernel(const float* __restrict__ glb_pos,
                 const float* __restrict__ glb_vel,
                 const float* __restrict__ root) {
    const int b = blockIdx.x;
    const int tid = threadIdx.x;
    __shared__ float wsx[8], wsy[8], wsz[8];
    const int lane = tid & 31, warp = tid >> 5;

    // e[t] = rot(inv[t-1], vel[t-1, joint0]), e[0] = 0; 4 t-steps per thread
    float ex[4], ey[4], ez[4];
    #pragma unroll
    for (int k = 0; k < 4; k++) {
        int t = tid * 4 + k;
        ex[k] = ey[k] = ez[k] = 0.0f;
        if (t >= 1) {
            int s = t - 1;
            float4 q = __ldg((const float4*)(root + (size_t)(b * TT + s) * 4));
            float4 v = __ldg((const float4*)(glb_vel +
                             (size_t)(b * (TT - 1) + s) * JJ * 3));  // joint0 (+pad)
            qrotate(q.x, -q.y, -q.z, -q.w, v.x, v.y, v.z, ex[k], ey[k], ez[k]);
        }
    }
    // local inclusive
    #pragma unroll
    for (int k = 1; k < 4; k++) { ex[k] += ex[k-1]; ey[k] += ey[k-1]; ez[k] += ez[k-1]; }
    const float thx = ex[3], thy = ey[3], thz = ez[3];

    // warp-inclusive scan of per-thread sums
    float sx = thx, sy = thy, sz = thz;
    #pragma unroll
    for (int d = 1; d < 32; d <<= 1) {
        float nx = __shfl_up_sync(0xffffffffu, sx, d);
        float ny = __shfl_up_sync(0xffffffffu, sy, d);
        float nz = __shfl_up_sync(0xffffffffu, sz, d);
        if (lane >= d) { sx += nx; sy += ny; sz += nz; }
    }
    if (lane == 31) { wsx[warp] = sx; wsy[warp] = sy; wsz[warp] = sz; }
    __syncthreads();
    if (tid == 0) {
        float ax = 0, ay = 0, az = 0;
        #pragma unroll
        for (int w2 = 0; w2 < 8; w2++) {
            float tx = wsx[w2], ty = wsy[w2], tz = wsz[w2];
            wsx[w2] = ax; wsy[w2] = ay; wsz[w2] = az;
            ax += tx; ay += ty; az += tz;
        }
    }
    __syncthreads();

    // base = rot(inv[b,0], pos[b,0,joint0])
    float4 q0 = __ldg((const float4*)(root + (size_t)b * TT * 4));
    float4 p0 = __ldg((const float4*)(glb_pos + (size_t)b * TT * JJ * 3));
    float bx, by, bz;
    qrotate(q0.x, -q0.y, -q0.z, -q0.w, p0.x, p0.y, p0.z, bx, by, bz);

    const float offx = bx + wsx[warp] + (sx - thx);
    const float offy = by + wsy[warp] + (sy - thy);
    const float offz = bz + wsz[warp] + (sz - thz);
    #pragma unroll
    for (int k = 0; k < 4; k++) {
        d_traj[b * TT + tid * 4 + k] =
            make_float4(offx + ex[k], offy + ey[k], offz + ez[k], 0.0f);
    }
}

// Kernel 2: elementwise over (b,t,j) — the proven R1 layout: 1 element/thread,
// scalar pos loads (perfectly coalesced 32b), float4 rot traffic.
__global__ void __launch_bounds__(256)
main_kernel(const float* __restrict__ glb_pos,
            const float* __restrict__ glb_rot,
            const float* __restrict__ root,
            float* __restrict__ out) {
    const int idx = blockIdx.x * blockDim.x + threadIdx.x;  // 0 .. TOTAL-1
    const int pair = idx >> 5;  // (b*T + t), since J == 32

    // inv root quaternion (warp-uniform broadcast)
    const float4 q = __ldg((const float4*)(root + (size_t)pair * 4));
    const float w = q.x, x = -q.y, y = -q.z, z = -q.w;

    // --- position path ---
    const float* p = glb_pos + (size_t)idx * 3;
    float px, py, pz;
    qrotate(w, x, y, z, __ldg(p), __ldg(p + 1), __ldg(p + 2), px, py, pz);

    const float4 tr = __ldg(&d_traj[pair]);   // safe: d_traj immutable in this kernel

    float* op = out + (size_t)idx * 3;
    op[0] = px + tr.x;
    op[1] = py;
    op[2] = pz + tr.z;

    // --- rotation path: standardize(inv ⊗ glb_rot) ---
    const float4 g = __ldg((const float4*)(glb_rot + (size_t)idx * 4));
    float rw = w * g.x - x * g.y - y * g.z - z * g.w;
    float rx = w * g.y + x * g.x + y * g.w - z * g.z;
    float ry = w * g.z - x * g.w + y * g.x + z * g.y;
    float rz = w * g.w + x * g.z - y * g.y + z * g.x;
    float s = (rw < 0.0f) ? -1.0f : 1.0f;
    ((float4*)(out + (size_t)TOTAL * 3))[idx] =
        make_float4(s * rw, s * rx, s * ry, s * rz);
}

extern "C" void kernel_launch(void* const* d_in, const int* in_sizes, int n_in,
                              void* d_out, int out_size) {
    const float* glb_pos = (const float*)d_in[0];
    const float* glb_rot = (const float*)d_in[1];
    const float* glb_vel = (const float*)d_in[2];
    const float* root    = (const float*)d_in[3];
    float* out = (float*)d_out;

    traj_scan_kernel<<<BB, 256>>>(glb_pos, glb_vel, root);
    main_kernel<<<TOTAL / 256, 256>>>(glb_pos, glb_rot, root, out);
}